// round 3
// baseline (speedup 1.0000x reference)
#include <cuda_runtime.h>

// Fixed shapes from setup_inputs
#define LQ 512   // sequence length
#define DD 256   // per-tensor feature dim
#define FD 512   // 2*DD (MLP hidden)
#define NB 2     // batch
#define NH 8     // heads
#define DK 64    // head dim

// Scratch (no cudaMalloc allowed)
__device__ float g_A[NB * LQ * FD];   // d1 @ W1[:DD]
__device__ float g_C[NB * LQ * FD];   // d0 @ W1[DD:] + b1
__device__ float g_D[NB * LQ * LQ];   // decisions: 0 or -1e9

typedef unsigned long long u64;

// Packed f32x2 ops (sm_100+): two fp32 lanes per instruction on the fma pipe.
// NOTE: max.f32x2 does NOT exist in ptxas — relu is done on scalar halves.
#define FFMA2(d,a,b,c) asm("fma.rn.f32x2 %0,%1,%2,%3;" : "=l"(d) : "l"(a),"l"(b),"l"(c))
#define FADD2(d,a,b)   asm("add.rn.f32x2 %0,%1,%2;"    : "=l"(d) : "l"(a),"l"(b))

__device__ __forceinline__ float2 unpk(u64 p) {
    float lo, hi;
    asm("mov.b64 {%0,%1},%2;" : "=f"(lo), "=f"(hi) : "l"(p));
    return make_float2(lo, hi);
}
__device__ __forceinline__ u64 pk(float lo, float hi) {
    u64 d;
    asm("mov.b64 %0,{%1,%2};" : "=l"(d) : "f"(lo), "f"(hi));
    return d;
}

// ---------------------------------------------------------------------------
// Kernel 1: A = d1 @ W1_top ; C = d0 @ W1_bot + b1
// M=1024 rows, N=512, K=256. Tile 32m x 64n, 128 threads, per-thread 4x4,
// accumulators packed along m (i-pairs), B duplicated in smem for broadcast.
// ---------------------------------------------------------------------------
__global__ __launch_bounds__(128) void gemm_ac_kernel(
    const float* __restrict__ d1, const float* __restrict__ d0,
    const float* __restrict__ W1, const float* __restrict__ b1)
{
    const int z = blockIdx.z;                       // 0 -> A, 1 -> C
    const float* src = z ? d0 : d1;                 // [1024, 256]
    const float* W   = W1 + (z ? DD * FD : 0);      // [256, 512]
    float* dst = z ? g_C : g_A;

    __shared__ __align__(16) float As_T[32][36];    // [k][m] transposed
    __shared__ __align__(16) float Bs2[32][130];    // [k][2n] duplicated

    const int m0 = blockIdx.y * 32;
    const int n0 = blockIdx.x * 64;
    const int t  = threadIdx.x;
    const int tx = t & 15;          // 16 j-groups of 4
    const int ty = t >> 4;          // 8  i-groups of 4

    u64 acc[2][4] = {};             // pairs along i

    for (int k0 = 0; k0 < DD; k0 += 32) {
        __syncthreads();
        // A tile 32m x 32k -> transposed store
        #pragma unroll
        for (int r = 0; r < 8; r++) {
            int lin = t + r * 128;
            int mm = lin >> 5, kk = lin & 31;
            As_T[kk][mm] = src[(m0 + mm) * DD + k0 + kk];
        }
        // W tile 32k x 64n -> duplicated store
        #pragma unroll
        for (int r = 0; r < 16; r++) {
            int lin = t + r * 128;
            int kk = lin >> 6, nn = lin & 63;
            float v = W[(k0 + kk) * FD + n0 + nn];
            *(float2*)&Bs2[kk][2 * nn] = make_float2(v, v);
        }
        __syncthreads();

        #pragma unroll
        for (int kk = 0; kk < 32; kk++) {
            ulonglong2 ap = *(const ulonglong2*)&As_T[kk][ty * 4];
            #pragma unroll
            for (int j = 0; j < 4; j++) {
                u64 bd = *(const u64*)&Bs2[kk][2 * (tx * 4 + j)];
                FFMA2(acc[0][j], ap.x, bd, acc[0][j]);
                FFMA2(acc[1][j], ap.y, bd, acc[1][j]);
            }
        }
    }

    float4 bv = make_float4(0.f, 0.f, 0.f, 0.f);
    if (z) bv = *(const float4*)&b1[n0 + tx * 4];

    #pragma unroll
    for (int ip = 0; ip < 2; ip++) {
        float2 v[4];
        #pragma unroll
        for (int j = 0; j < 4; j++) v[j] = unpk(acc[ip][j]);
        int ii = m0 + ty * 4 + 2 * ip;
        float4 r0 = make_float4(v[0].x + bv.x, v[1].x + bv.y, v[2].x + bv.z, v[3].x + bv.w);
        float4 r1 = make_float4(v[0].y + bv.x, v[1].y + bv.y, v[2].y + bv.z, v[3].y + bv.w);
        *(float4*)&dst[(ii    ) * FD + n0 + tx * 4] = r0;
        *(float4*)&dst[(ii + 1) * FD + n0 + tx * 4] = r1;
    }
}

// ---------------------------------------------------------------------------
// Kernel 2: decisions[b,i,j] = (sum_f relu(A[b,i,f]+C[b,j,f])*w2d[f] + b2d > 0)
//           ? -1e9 : 0
// Tile 32i x 64j, 128 threads, packed pairs along i, C + w duplicated in smem.
// relu on scalar halves (FMNMX, alu pipe). Chunk-partial accumulation keeps
// R1's exact-match numerics.
// ---------------------------------------------------------------------------
__global__ __launch_bounds__(128) void decisions_kernel(
    const float* __restrict__ W2, const float* __restrict__ b2)
{
    const int b  = blockIdx.z;
    const int i0 = blockIdx.y * 32;
    const int j0 = blockIdx.x * 64;
    const float* Ab = g_A + b * LQ * FD;
    const float* Cb = g_C + b * LQ * FD;

    __shared__ __align__(16) float As_T[32][36];    // [f][i]
    __shared__ __align__(16) float Cs2[32][130];    // [f][2j] duplicated
    __shared__ __align__(16) float ws2[2 * FD];     // duplicated w2 diff

    const int t  = threadIdx.x;
    const int tx = t & 15;
    const int ty = t >> 4;

    for (int f = t; f < FD; f += 128) {
        float w = W2[2 * f + 1] - W2[2 * f];
        ws2[2 * f] = w; ws2[2 * f + 1] = w;
    }

    u64 acc[2][4] = {};

    for (int f0 = 0; f0 < FD; f0 += 32) {
        __syncthreads();
        #pragma unroll
        for (int r = 0; r < 8; r++) {
            int lin = t + r * 128;
            int ii = lin >> 5, ff = lin & 31;
            As_T[ff][ii] = Ab[(i0 + ii) * FD + f0 + ff];
        }
        #pragma unroll
        for (int r = 0; r < 16; r++) {
            int lin = t + r * 128;
            int jj = lin >> 5, ff = lin & 31;
            float v = Cb[(j0 + jj) * FD + f0 + ff];
            *(float2*)&Cs2[ff][2 * jj] = make_float2(v, v);
        }
        __syncthreads();

        u64 accC[2][4] = {};
        #pragma unroll
        for (int kk = 0; kk < 32; kk++) {
            ulonglong2 ap = *(const ulonglong2*)&As_T[kk][ty * 4];
            u64 wd = *(const u64*)&ws2[2 * (f0 + kk)];
            #pragma unroll
            for (int j = 0; j < 4; j++) {
                u64 cd = *(const u64*)&Cs2[kk][2 * (tx * 4 + j)];
                u64 s0, s1;
                FADD2(s0, ap.x, cd);
                FADD2(s1, ap.y, cd);
                float2 h0 = unpk(s0), h1 = unpk(s1);
                u64 r0 = pk(fmaxf(h0.x, 0.f), fmaxf(h0.y, 0.f));
                u64 r1 = pk(fmaxf(h1.x, 0.f), fmaxf(h1.y, 0.f));
                FFMA2(accC[0][j], r0, wd, accC[0][j]);
                FFMA2(accC[1][j], r1, wd, accC[1][j]);
            }
        }
        #pragma unroll
        for (int ip = 0; ip < 2; ip++)
            #pragma unroll
            for (int j = 0; j < 4; j++)
                FADD2(acc[ip][j], acc[ip][j], accC[ip][j]);
    }

    const float b2d = b2[1] - b2[0];
    float* Db = g_D + b * LQ * LQ;
    #pragma unroll
    for (int ip = 0; ip < 2; ip++) {
        float2 v[4];
        #pragma unroll
        for (int j = 0; j < 4; j++) v[j] = unpk(acc[ip][j]);
        int ii = i0 + ty * 4 + 2 * ip;
        float4 r0 = make_float4(
            (v[0].x + b2d > 0.f) ? -1e9f : 0.f, (v[1].x + b2d > 0.f) ? -1e9f : 0.f,
            (v[2].x + b2d > 0.f) ? -1e9f : 0.f, (v[3].x + b2d > 0.f) ? -1e9f : 0.f);
        float4 r1 = make_float4(
            (v[0].y + b2d > 0.f) ? -1e9f : 0.f, (v[1].y + b2d > 0.f) ? -1e9f : 0.f,
            (v[2].y + b2d > 0.f) ? -1e9f : 0.f, (v[3].y + b2d > 0.f) ? -1e9f : 0.f);
        *(float4*)&Db[(ii    ) * LQ + j0 + tx * 4] = r0;
        *(float4*)&Db[(ii + 1) * LQ + j0 + tx * 4] = r1;
    }
}

// ---------------------------------------------------------------------------
// Kernel 3: out[b,n,i,j] = dot(q[b,n,i,:], k[b,n,j,:]) / 8 + D[b,i,j]
// Tile 32i x 64j per (b,n). Same packed microkernel, K duplicated in smem.
// ---------------------------------------------------------------------------
__global__ __launch_bounds__(128) void attn_kernel(
    const float* __restrict__ q, const float* __restrict__ k,
    float* __restrict__ out)
{
    const int bn = blockIdx.z;          // b*NH + n
    const int b  = bn >> 3;
    const int i0 = blockIdx.y * 32;
    const int j0 = blockIdx.x * 64;
    const float* Q = q + bn * LQ * DK;
    const float* K = k + bn * LQ * DK;

    __shared__ __align__(16) float Qs_T[32][36];    // [d][i]
    __shared__ __align__(16) float Ks2[32][130];    // [d][2j] duplicated

    const int t  = threadIdx.x;
    const int tx = t & 15;
    const int ty = t >> 4;

    u64 acc[2][4] = {};

    for (int d0 = 0; d0 < DK; d0 += 32) {
        __syncthreads();
        #pragma unroll
        for (int r = 0; r < 8; r++) {
            int lin = t + r * 128;
            int ii = lin >> 5, dd = lin & 31;
            Qs_T[dd][ii] = Q[(i0 + ii) * DK + d0 + dd];
        }
        #pragma unroll
        for (int r = 0; r < 16; r++) {
            int lin = t + r * 128;
            int jj = lin >> 5, dd = lin & 31;
            float v = K[(j0 + jj) * DK + d0 + dd];
            *(float2*)&Ks2[dd][2 * jj] = make_float2(v, v);
        }
        __syncthreads();

        #pragma unroll
        for (int kk = 0; kk < 32; kk++) {
            ulonglong2 ap = *(const ulonglong2*)&Qs_T[kk][ty * 4];
            #pragma unroll
            for (int j = 0; j < 4; j++) {
                u64 kd = *(const u64*)&Ks2[kk][2 * (tx * 4 + j)];
                FFMA2(acc[0][j], ap.x, kd, acc[0][j]);
                FFMA2(acc[1][j], ap.y, kd, acc[1][j]);
            }
        }
    }

    const float* Db = g_D + b * LQ * LQ;
    float* O = out + bn * LQ * LQ;
    #pragma unroll
    for (int ip = 0; ip < 2; ip++) {
        float2 v[4];
        #pragma unroll
        for (int j = 0; j < 4; j++) v[j] = unpk(acc[ip][j]);
        int ii = i0 + ty * 4 + 2 * ip;
        float4 d0v = *(const float4*)&Db[(ii    ) * LQ + j0 + tx * 4];
        float4 d1v = *(const float4*)&Db[(ii + 1) * LQ + j0 + tx * 4];
        float4 r0 = make_float4(v[0].x * 0.125f + d0v.x, v[1].x * 0.125f + d0v.y,
                                v[2].x * 0.125f + d0v.z, v[3].x * 0.125f + d0v.w);
        float4 r1 = make_float4(v[0].y * 0.125f + d1v.x, v[1].y * 0.125f + d1v.y,
                                v[2].y * 0.125f + d1v.z, v[3].y * 0.125f + d1v.w);
        *(float4*)&O[(ii    ) * LQ + j0 + tx * 4] = r0;
        *(float4*)&O[(ii + 1) * LQ + j0 + tx * 4] = r1;
    }
}

// ---------------------------------------------------------------------------
// Inputs (metadata order): q, k, d0, d1, W1, b1, W2, b2
// ---------------------------------------------------------------------------
extern "C" void kernel_launch(void* const* d_in, const int* in_sizes, int n_in,
                              void* d_out, int out_size)
{
    const float* q  = (const float*)d_in[0];   // [2,8,512,64]
    const float* k  = (const float*)d_in[1];   // [2,8,512,64]
    const float* d0 = (const float*)d_in[2];   // [2,512,256]
    const float* d1 = (const float*)d_in[3];   // [2,512,256]
    const float* W1 = (const float*)d_in[4];   // [512,512]
    const float* b1 = (const float*)d_in[5];   // [512]
    const float* W2 = (const float*)d_in[6];   // [512,2]
    const float* b2 = (const float*)d_in[7];   // [2]
    float* out = (float*)d_out;                // [2,8,512,512]

    (void)in_sizes; (void)n_in; (void)out_size;

    gemm_ac_kernel  <<<dim3(FD / 64, (NB * LQ) / 32, 2),      128>>>(d1, d0, W1, b1);
    decisions_kernel<<<dim3(LQ / 64, LQ / 32, NB),            128>>>(W2, b2);
    attn_kernel     <<<dim3(LQ / 64, LQ / 32, NB * NH),       128>>>(q, k, out);
}

// round 4
// speedup vs baseline: 1.7293x; 1.7293x over previous
#include <cuda_runtime.h>

// Fixed shapes from setup_inputs
#define LQ 512   // sequence length
#define DD 256   // per-tensor feature dim
#define FD 512   // 2*DD (MLP hidden)
#define NB 2     // batch
#define NH 8     // heads
#define DK 64    // head dim

// Scratch (no cudaMalloc allowed)
__device__ float g_A[NB * LQ * FD];   // d1 @ W1[:DD]
__device__ float g_C[NB * LQ * FD];   // d0 @ W1[DD:] + b1
__device__ float g_D[NB * LQ * LQ];   // decisions: 0 or -1e9

typedef unsigned long long u64;

// Packed f32x2 (sm_100+): 2 fp32 lanes per fma-pipe instruction.
#define FFMA2(d,a,b,c) asm("fma.rn.f32x2 %0,%1,%2,%3;" : "=l"(d) : "l"(a),"l"(b),"l"(c))
#define FADD2(d,a,b)   asm("add.rn.f32x2 %0,%1,%2;"    : "=l"(d) : "l"(a),"l"(b))

__device__ __forceinline__ float2 unpk(u64 p) {
    float lo, hi;
    asm("mov.b64 {%0,%1},%2;" : "=f"(lo), "=f"(hi) : "l"(p));
    return make_float2(lo, hi);
}
__device__ __forceinline__ u64 pk(float lo, float hi) {
    u64 d;
    asm("mov.b64 %0,{%1,%2};" : "=l"(d) : "f"(lo), "f"(hi));
    return d;
}

// Shared tile geometry (all kernels):
//   64i x 64j tile, 256 threads, per-thread 4i x 4j (j-packed pairs), K-chunk 32.
//   iy = t>>4 (0..15), jx = t&15 (0..15).
//   As2: [32][132] floats, duplicated pairs As2[k][2i] = {a,a}; row 528B (16B-aligned).
//        Inner read: 2x LDS.128, only 2 iy per warp -> broadcast, conflict-free.
//   Bs : [32][68] floats, plain [k][j]; row 272B (16B-aligned).
//        Inner read: 1x LDS.128 at 16B lane stride -> conflict-free.
#define AP 132
#define BP 68

// ---------------------------------------------------------------------------
// Kernel 1: A = d1 @ W1_top ; C = d0 @ W1_bot + b1   (M=1024, N=512, K=256)
// ---------------------------------------------------------------------------
__global__ __launch_bounds__(256) void gemm_ac_kernel(
    const float* __restrict__ d1, const float* __restrict__ d0,
    const float* __restrict__ W1, const float* __restrict__ b1)
{
    const int z = blockIdx.z;                       // 0 -> A, 1 -> C
    const float* src = z ? d0 : d1;                 // [1024, 256]
    const float* W   = W1 + (z ? DD * FD : 0);      // [256, 512]
    float* dst = z ? g_C : g_A;

    __shared__ __align__(16) float As2[32 * AP];
    __shared__ __align__(16) float Bs[32 * BP];

    const int m0 = blockIdx.y * 64;
    const int n0 = blockIdx.x * 64;
    const int t  = threadIdx.x;
    const int jx = t & 15, iy = t >> 4;
    const int mm = t >> 2, kq = t & 3;              // A fill: 64 rows x 2 quads
    const int bk = t >> 3, nq = t & 7;              // B fill: 32 rows x 2 quads

    u64 acc[4][2] = {};

    for (int k0 = 0; k0 < DD; k0 += 32) {
        __syncthreads();
        #pragma unroll
        for (int r = 0; r < 2; r++) {
            int qd = kq + 4 * r;
            float4 v = *(const float4*)&src[(m0 + mm) * DD + k0 + qd * 4];
            *(float2*)&As2[(qd * 4 + 0) * AP + 2 * mm] = make_float2(v.x, v.x);
            *(float2*)&As2[(qd * 4 + 1) * AP + 2 * mm] = make_float2(v.y, v.y);
            *(float2*)&As2[(qd * 4 + 2) * AP + 2 * mm] = make_float2(v.z, v.z);
            *(float2*)&As2[(qd * 4 + 3) * AP + 2 * mm] = make_float2(v.w, v.w);
        }
        #pragma unroll
        for (int r = 0; r < 2; r++)
            *(float4*)&Bs[bk * BP + nq * 8 + r * 4] =
                *(const float4*)&W[(k0 + bk) * FD + n0 + nq * 8 + r * 4];
        __syncthreads();

        #pragma unroll
        for (int kk = 0; kk < 32; kk++) {
            ulonglong2 a01 = *(const ulonglong2*)&As2[kk * AP + iy * 8];
            ulonglong2 a23 = *(const ulonglong2*)&As2[kk * AP + iy * 8 + 4];
            ulonglong2 bv  = *(const ulonglong2*)&Bs[kk * BP + jx * 4];
            FFMA2(acc[0][0], a01.x, bv.x, acc[0][0]);
            FFMA2(acc[0][1], a01.x, bv.y, acc[0][1]);
            FFMA2(acc[1][0], a01.y, bv.x, acc[1][0]);
            FFMA2(acc[1][1], a01.y, bv.y, acc[1][1]);
            FFMA2(acc[2][0], a23.x, bv.x, acc[2][0]);
            FFMA2(acc[2][1], a23.x, bv.y, acc[2][1]);
            FFMA2(acc[3][0], a23.y, bv.x, acc[3][0]);
            FFMA2(acc[3][1], a23.y, bv.y, acc[3][1]);
        }
    }

    float4 bv4 = make_float4(0.f, 0.f, 0.f, 0.f);
    if (z) bv4 = *(const float4*)&b1[n0 + jx * 4];

    #pragma unroll
    for (int i = 0; i < 4; i++) {
        float2 p0 = unpk(acc[i][0]), p1 = unpk(acc[i][1]);
        float4 r = make_float4(p0.x + bv4.x, p0.y + bv4.y, p1.x + bv4.z, p1.y + bv4.w);
        *(float4*)&dst[(m0 + iy * 4 + i) * FD + n0 + jx * 4] = r;
    }
}

// ---------------------------------------------------------------------------
// Kernel 2: decisions[b,i,j] = (sum_f relu(A[b,i,f]+C[b,j,f])*w2d[f] + b2d > 0)
//           ? -1e9 : 0.   relu on scalar halves (alu pipe); chunk-32 partials
//           reproduce R1's exact summation order.
// ---------------------------------------------------------------------------
__global__ __launch_bounds__(256) void decisions_kernel(
    const float* __restrict__ W2, const float* __restrict__ b2)
{
    const int b  = blockIdx.z;
    const int i0 = blockIdx.y * 64;
    const int j0 = blockIdx.x * 64;
    const float* Ab = g_A + b * LQ * FD;
    const float* Cb = g_C + b * LQ * FD;

    __shared__ __align__(16) float As2[32 * AP];
    __shared__ __align__(16) float Cs[32 * BP];
    __shared__ __align__(16) float ws2[2 * FD];

    const int t  = threadIdx.x;
    const int jx = t & 15, iy = t >> 4;
    const int mm = t >> 2, kq = t & 3;

    for (int f = t; f < FD; f += 256) {
        float w = W2[2 * f + 1] - W2[2 * f];
        ws2[2 * f] = w; ws2[2 * f + 1] = w;
    }

    u64 acc[4][2] = {};

    for (int f0 = 0; f0 < FD; f0 += 32) {
        __syncthreads();
        #pragma unroll
        for (int r = 0; r < 2; r++) {
            int qd = kq + 4 * r;
            float4 v = *(const float4*)&Ab[(i0 + mm) * FD + f0 + qd * 4];
            *(float2*)&As2[(qd * 4 + 0) * AP + 2 * mm] = make_float2(v.x, v.x);
            *(float2*)&As2[(qd * 4 + 1) * AP + 2 * mm] = make_float2(v.y, v.y);
            *(float2*)&As2[(qd * 4 + 2) * AP + 2 * mm] = make_float2(v.z, v.z);
            *(float2*)&As2[(qd * 4 + 3) * AP + 2 * mm] = make_float2(v.w, v.w);
            float4 c = *(const float4*)&Cb[(j0 + mm) * FD + f0 + qd * 4];
            Cs[(qd * 4 + 0) * BP + mm] = c.x;       // transposed [f][j]
            Cs[(qd * 4 + 1) * BP + mm] = c.y;
            Cs[(qd * 4 + 2) * BP + mm] = c.z;
            Cs[(qd * 4 + 3) * BP + mm] = c.w;
        }
        __syncthreads();

        u64 accC[4][2] = {};
        #pragma unroll
        for (int kk = 0; kk < 32; kk++) {
            ulonglong2 a01 = *(const ulonglong2*)&As2[kk * AP + iy * 8];
            ulonglong2 a23 = *(const ulonglong2*)&As2[kk * AP + iy * 8 + 4];
            ulonglong2 cv  = *(const ulonglong2*)&Cs[kk * BP + jx * 4];
            u64 wd = *(const u64*)&ws2[2 * (f0 + kk)];
            u64 s;  float2 h;  u64 rr;
            FADD2(s, a01.x, cv.x); h = unpk(s); rr = pk(fmaxf(h.x,0.f), fmaxf(h.y,0.f)); FFMA2(accC[0][0], rr, wd, accC[0][0]);
            FADD2(s, a01.x, cv.y); h = unpk(s); rr = pk(fmaxf(h.x,0.f), fmaxf(h.y,0.f)); FFMA2(accC[0][1], rr, wd, accC[0][1]);
            FADD2(s, a01.y, cv.x); h = unpk(s); rr = pk(fmaxf(h.x,0.f), fmaxf(h.y,0.f)); FFMA2(accC[1][0], rr, wd, accC[1][0]);
            FADD2(s, a01.y, cv.y); h = unpk(s); rr = pk(fmaxf(h.x,0.f), fmaxf(h.y,0.f)); FFMA2(accC[1][1], rr, wd, accC[1][1]);
            FADD2(s, a23.x, cv.x); h = unpk(s); rr = pk(fmaxf(h.x,0.f), fmaxf(h.y,0.f)); FFMA2(accC[2][0], rr, wd, accC[2][0]);
            FADD2(s, a23.x, cv.y); h = unpk(s); rr = pk(fmaxf(h.x,0.f), fmaxf(h.y,0.f)); FFMA2(accC[2][1], rr, wd, accC[2][1]);
            FADD2(s, a23.y, cv.x); h = unpk(s); rr = pk(fmaxf(h.x,0.f), fmaxf(h.y,0.f)); FFMA2(accC[3][0], rr, wd, accC[3][0]);
            FADD2(s, a23.y, cv.y); h = unpk(s); rr = pk(fmaxf(h.x,0.f), fmaxf(h.y,0.f)); FFMA2(accC[3][1], rr, wd, accC[3][1]);
        }
        #pragma unroll
        for (int i = 0; i < 4; i++) {
            FADD2(acc[i][0], acc[i][0], accC[i][0]);
            FADD2(acc[i][1], acc[i][1], accC[i][1]);
        }
    }

    const float b2d = b2[1] - b2[0];
    float* Db = g_D + b * LQ * LQ;
    #pragma unroll
    for (int i = 0; i < 4; i++) {
        float2 p0 = unpk(acc[i][0]), p1 = unpk(acc[i][1]);
        float4 r = make_float4(
            (p0.x + b2d > 0.f) ? -1e9f : 0.f, (p0.y + b2d > 0.f) ? -1e9f : 0.f,
            (p1.x + b2d > 0.f) ? -1e9f : 0.f, (p1.y + b2d > 0.f) ? -1e9f : 0.f);
        *(float4*)&Db[(i0 + iy * 4 + i) * LQ + j0 + jx * 4] = r;
    }
}

// ---------------------------------------------------------------------------
// Kernel 3: out[b,n,i,j] = dot(q[b,n,i,:], k[b,n,j,:]) * 0.125 + D[b,i,j]
// ---------------------------------------------------------------------------
__global__ __launch_bounds__(256) void attn_kernel(
    const float* __restrict__ q, const float* __restrict__ k,
    float* __restrict__ out)
{
    const int bn = blockIdx.z;          // b*NH + n
    const int b  = bn >> 3;
    const int i0 = blockIdx.y * 64;
    const int j0 = blockIdx.x * 64;
    const float* Q = q + bn * LQ * DK;
    const float* K = k + bn * LQ * DK;

    __shared__ __align__(16) float As2[32 * AP];
    __shared__ __align__(16) float Ks[32 * BP];

    const int t  = threadIdx.x;
    const int jx = t & 15, iy = t >> 4;
    const int mm = t >> 2, kq = t & 3;

    u64 acc[4][2] = {};

    for (int d0 = 0; d0 < DK; d0 += 32) {
        __syncthreads();
        #pragma unroll
        for (int r = 0; r < 2; r++) {
            int qd = kq + 4 * r;
            float4 v = *(const float4*)&Q[(i0 + mm) * DK + d0 + qd * 4];
            *(float2*)&As2[(qd * 4 + 0) * AP + 2 * mm] = make_float2(v.x, v.x);
            *(float2*)&As2[(qd * 4 + 1) * AP + 2 * mm] = make_float2(v.y, v.y);
            *(float2*)&As2[(qd * 4 + 2) * AP + 2 * mm] = make_float2(v.z, v.z);
            *(float2*)&As2[(qd * 4 + 3) * AP + 2 * mm] = make_float2(v.w, v.w);
            float4 c = *(const float4*)&K[(j0 + mm) * DK + d0 + qd * 4];
            Ks[(qd * 4 + 0) * BP + mm] = c.x;       // transposed [d][j]
            Ks[(qd * 4 + 1) * BP + mm] = c.y;
            Ks[(qd * 4 + 2) * BP + mm] = c.z;
            Ks[(qd * 4 + 3) * BP + mm] = c.w;
        }
        __syncthreads();

        #pragma unroll
        for (int kk = 0; kk < 32; kk++) {
            ulonglong2 a01 = *(const ulonglong2*)&As2[kk * AP + iy * 8];
            ulonglong2 a23 = *(const ulonglong2*)&As2[kk * AP + iy * 8 + 4];
            ulonglong2 bv  = *(const ulonglong2*)&Ks[kk * BP + jx * 4];
            FFMA2(acc[0][0], a01.x, bv.x, acc[0][0]);
            FFMA2(acc[0][1], a01.x, bv.y, acc[0][1]);
            FFMA2(acc[1][0], a01.y, bv.x, acc[1][0]);
            FFMA2(acc[1][1], a01.y, bv.y, acc[1][1]);
            FFMA2(acc[2][0], a23.x, bv.x, acc[2][0]);
            FFMA2(acc[2][1], a23.x, bv.y, acc[2][1]);
            FFMA2(acc[3][0], a23.y, bv.x, acc[3][0]);
            FFMA2(acc[3][1], a23.y, bv.y, acc[3][1]);
        }
    }

    const float* Db = g_D + b * LQ * LQ;
    float* O = out + bn * LQ * LQ;
    #pragma unroll
    for (int i = 0; i < 4; i++) {
        int row = i0 + iy * 4 + i;
        float4 dv = *(const float4*)&Db[row * LQ + j0 + jx * 4];
        float2 p0 = unpk(acc[i][0]), p1 = unpk(acc[i][1]);
        float4 r = make_float4(p0.x * 0.125f + dv.x, p0.y * 0.125f + dv.y,
                               p1.x * 0.125f + dv.z, p1.y * 0.125f + dv.w);
        *(float4*)&O[row * LQ + j0 + jx * 4] = r;
    }
}

// ---------------------------------------------------------------------------
// Inputs (metadata order): q, k, d0, d1, W1, b1, W2, b2
// ---------------------------------------------------------------------------
extern "C" void kernel_launch(void* const* d_in, const int* in_sizes, int n_in,
                              void* d_out, int out_size)
{
    const float* q  = (const float*)d_in[0];   // [2,8,512,64]
    const float* k  = (const float*)d_in[1];   // [2,8,512,64]
    const float* d0 = (const float*)d_in[2];   // [2,512,256]
    const float* d1 = (const float*)d_in[3];   // [2,512,256]
    const float* W1 = (const float*)d_in[4];   // [512,512]
    const float* b1 = (const float*)d_in[5];   // [512]
    const float* W2 = (const float*)d_in[6];   // [512,2]
    const float* b2 = (const float*)d_in[7];   // [2]
    float* out = (float*)d_out;                // [2,8,512,512]

    (void)in_sizes; (void)n_in; (void)out_size;

    gemm_ac_kernel  <<<dim3(FD / 64, (NB * LQ) / 64, 2),   256>>>(d1, d0, W1, b1);
    decisions_kernel<<<dim3(LQ / 64, LQ / 64, NB),          256>>>(W2, b2);
    attn_kernel     <<<dim3(LQ / 64, LQ / 64, NB * NH),     256>>>(q, k, out);
}